// round 4
// baseline (speedup 1.0000x reference)
#include <cuda_runtime.h>
#include <cstdint>

typedef unsigned long long ull;

#define NB      16
#define NENT    100000
#define NTILES  3125           // NENT / 32
#define GRID    296            // exactly 2 blocks per SM (148 SMs)
#define TPB     192            // 6 warps
#define NW      6
#define ROWF4   33             // float4 stride per staged row (pad -> conflict-free)
#define XS_F4   (32 * ROWF4)   // per-warp staging float4 count
#define DBS     17             // dist buffer stride (floats)
// dynamic smem: staging NW*1056*16 = 101376 B + dist buf NW*16*17*4 = 6528 B
#define SMEM_BYTES (NW * XS_F4 * 16 + NW * 16 * DBS * 4)

// ---------------- device scratch (allocation-free) ----------------
__device__ float    g_part[NB * GRID];
__device__ unsigned g_ctr;     // tile work queue
__device__ unsigned g_done;    // grid barrier epoch counter (monotonic)

// ---------------- packed f32x2 helpers (sm_103a) ----------------
__device__ __forceinline__ ull add2(ull a, ull b) {
    ull r; asm("add.rn.f32x2 %0,%1,%2;" : "=l"(r) : "l"(a), "l"(b)); return r;
}
__device__ __forceinline__ ull fma2(ull a, ull b, ull c) {
    ull r; asm("fma.rn.f32x2 %0,%1,%2,%3;" : "=l"(r) : "l"(a), "l"(b), "l"(c)); return r;
}
__device__ __forceinline__ ull abs2(ull a) { return a & 0x7FFFFFFF7FFFFFFFull; }
__device__ __forceinline__ ull pk2(float a, float b) {
    ull r; asm("mov.b64 %0,{%1,%2};" : "=l"(r) : "f"(a), "f"(b)); return r;
}
__device__ __forceinline__ float2 upk(ull a) {
    float2 f; asm("mov.b64 {%0,%1},%2;" : "=f"(f.x), "=f"(f.y) : "l"(a)); return f;
}
__device__ __forceinline__ float wsum(float v) {
    #pragma unroll
    for (int o = 16; o; o >>= 1) v += __shfl_xor_sync(0xffffffffu, v, o);
    return v;
}

// =============== single fused kernel ===============
__global__ void __launch_bounds__(TPB, 2)
k_fused(const float* __restrict__ ent, const float* __restrict__ relemb,
        const int* __restrict__ e1w, const int* __restrict__ relw,
        float* __restrict__ out) {
    extern __shared__ float smf[];
    float4*     xs4  = (float4*)smf;                       // NW warps staging
    float*      dbuf = smf + NW * XS_F4 * 4;               // NW * 16*17 floats

    int tid = threadIdx.x, w = tid >> 5, l = tid & 31;
    float4*     xw   = xs4 + w * XS_F4;
    ulonglong2* xw2  = (ulonglong2*)xw;
    float*      dbw  = dbuf + w * (16 * DBS);

    __shared__ float sp[NW][NB];
    __shared__ float sinv_s[NB];

    // ---- index width detection (per-thread, no sync needed) ----
    int odd = e1w[1] | e1w[3] | e1w[5] | e1w[7] | e1w[9] | e1w[11] | e1w[13] | e1w[15];
    int is64 = (odd == 0);

    // ---- build h = norm(ent[e1[b]]) + norm(rel[rel[b]]) into warp-0 staging ----
    float4* hs4 = xs4;   // reuse, 16*32 float4 = 8KB
    for (int b = w; b < NB; b += NW) {
        long long ei, ri;
        if (is64) { ei = ((const long long*)e1w)[b]; ri = ((const long long*)relw)[b]; }
        else      { ei = (long long)e1w[b];          ri = (long long)relw[b]; }
        float4 a = ((const float4*)ent)[(size_t)ei * 32 + l];
        float sa = wsum(fmaf(a.x, a.x, fmaf(a.y, a.y, fmaf(a.z, a.z, a.w * a.w))));
        float ia = rsqrtf(fmaxf(sa, 1e-24f));
        float4 c = ((const float4*)relemb)[(size_t)ri * 32 + l];
        float sc = wsum(fmaf(c.x, c.x, fmaf(c.y, c.y, fmaf(c.z, c.z, c.w * c.w))));
        float ic = rsqrtf(fmaxf(sc, 1e-24f));
        float4 h;
        h.x = fmaf(a.x, ia, c.x * ic);
        h.y = fmaf(a.y, ia, c.y * ic);
        h.z = fmaf(a.z, ia, c.z * ic);
        h.w = fmaf(a.w, ia, c.w * ic);
        hs4[b * 32 + l] = h;
    }
    __syncthreads();

    // ---- h into registers: lane l holds b = l&15, dim-half p = l>>4 ----
    const int bm = l & 15, p = l >> 4;
    ull h2[32];
    {
        const ulonglong2* hp = (const ulonglong2*)hs4 + bm * 32 + p;
        #pragma unroll
        for (int k = 0; k < 16; k++) {
            ulonglong2 t = hp[2 * k];
            h2[2 * k] = t.x; h2[2 * k + 1] = t.y;
        }
    }
    __syncthreads();   // h reads done before warp 0's staging overwrites hs4

    float es[8];
    #pragma unroll
    for (int j = 0; j < 8; j++) es[j] = 0.0f;
    const int b0 = p * 8;

    // =============== phase 1: dist -> exp -> store ===============
    for (;;) {
        unsigned t = 0u;
        if (l == 0) t = atomicAdd(&g_ctr, 1u);
        t = __shfl_sync(0xffffffffu, t, 0);
        if (t >= (unsigned)NTILES) break;
        int base = (int)t * 32;

        __syncwarp();
        // stage 32 entity rows, coalesced loads, padded rows (conflict-free)
        const float4* rowp = (const float4*)ent + (size_t)base * 32 + l;
        #pragma unroll
        for (int r0 = 0; r0 < 32; r0 += 8) {
            float4 v[8];
            #pragma unroll
            for (int r = 0; r < 8; r++) v[r] = rowp[(r0 + r) * 32];
            #pragma unroll
            for (int r = 0; r < 8; r++) xw[(r0 + r) * ROWF4 + l] = v[r];
        }
        __syncwarp();

        // sumsq of my entity row (lane l owns entity base+l)
        const float4* myrow = xw + l * ROWF4;
        float s0 = 0.f, s1 = 0.f, s2 = 0.f, s3 = 0.f;
        #pragma unroll
        for (int j = 0; j < 32; j += 4) {
            float4 v0 = myrow[j], v1 = myrow[j+1], v2 = myrow[j+2], v3 = myrow[j+3];
            s0 = fmaf(v0.x, v0.x, fmaf(v0.y, v0.y, fmaf(v0.z, v0.z, fmaf(v0.w, v0.w, s0))));
            s1 = fmaf(v1.x, v1.x, fmaf(v1.y, v1.y, fmaf(v1.z, v1.z, fmaf(v1.w, v1.w, s1))));
            s2 = fmaf(v2.x, v2.x, fmaf(v2.y, v2.y, fmaf(v2.z, v2.z, fmaf(v2.w, v2.w, s2))));
            s3 = fmaf(v3.x, v3.x, fmaf(v3.y, v3.y, fmaf(v3.z, v3.z, fmaf(v3.w, v3.w, s3))));
        }
        float ss  = (s0 + s1) + (s2 + s3);
        float inv = -rsqrtf(fmaxf(ss, 1e-24f));   // diff = fma(x, -inv, h)

        #pragma unroll 1
        for (int eh = 0; eh < 2; eh++) {          // two half-batches of 16 entities
            #pragma unroll 2
            for (int ee = 0; ee < 16; ee++) {
                int e = eh * 16 + ee;
                float iv = __shfl_sync(0xffffffffu, inv, e);
                ull nI = pk2(iv, iv);
                const ulonglong2* xp = xw2 + e * ROWF4 + p;   // 2 uniform addrs/warp
                ull a0 = 0ull, a1 = 0ull;
                #pragma unroll
                for (int k = 0; k < 16; k++) {
                    ulonglong2 xx = xp[2 * k];
                    a0 = add2(a0, abs2(fma2(xx.x, nI, h2[2 * k])));
                    a1 = add2(a1, abs2(fma2(xx.y, nI, h2[2 * k + 1])));
                }
                float2 f = upk(add2(a0, a1));
                float s = f.x + f.y;
                s += __shfl_xor_sync(0xffffffffu, s, 16);     // both dim-halves
                if (l < 16) dbw[ee * DBS + l] = s;            // dist[b=l][entity e]
            }
            __syncwarp();
            // epilogue: lane handles (entity eh*16 + bm, b-range b0..b0+7)
            {
                int el = eh * 16 + bm;
                const float* drow = dbw + bm * DBS;
                #pragma unroll
                for (int j = 0; j < 8; j++) {
                    float ex = __expf(drow[b0 + j]);          // dist<=~34: no max pass
                    out[(size_t)(b0 + j) * NENT + base + el] = ex;
                    es[j] += ex;
                }
            }
            __syncwarp();
        }
    }

    // ---- per-warp half-warp reductions -> block partials ----
    #pragma unroll
    for (int j = 0; j < 8; j++) {
        float v = es[j];
        v += __shfl_xor_sync(0xffffffffu, v, 1);
        v += __shfl_xor_sync(0xffffffffu, v, 2);
        v += __shfl_xor_sync(0xffffffffu, v, 4);
        v += __shfl_xor_sync(0xffffffffu, v, 8);
        if (bm == 0) sp[w][b0 + j] = v;       // lanes 0 and 16 write their halves
    }
    __syncthreads();
    if (tid < NB) {
        float s = 0.f;
        #pragma unroll
        for (int ww = 0; ww < NW; ww++) s += sp[ww][tid];
        g_part[tid * GRID + blockIdx.x] = s;
    }

    // =============== grid-wide barrier (all 296 blocks co-resident) ===============
    __syncthreads();
    if (tid == 0) {
        __threadfence();
        unsigned old = atomicAdd(&g_done, 1u);
        unsigned target = (old / GRID + 1u) * GRID;
        if (old % GRID == GRID - 1u) g_ctr = 0u;   // reset queue for next replay
        unsigned d;
        do {
            asm volatile("ld.global.acquire.gpu.u32 %0, [%1];" : "=r"(d) : "l"(&g_done));
        } while (d < target);
    }
    __syncthreads();

    // ---- reduce partials -> 1/sum per row ----
    for (int b = w; b < NB; b += NW) {
        float s = 0.f;
        for (int i = l; i < GRID; i += 32) s += g_part[b * GRID + i];
        s = wsum(s);
        if (l == 0) sinv_s[b] = 1.0f / s;
    }
    __syncthreads();

    // =============== phase 3: normalize in place (L2-hot) ===============
    {
        const int total4 = NB * NENT / 4;            // 400000
        const int chunk  = (total4 + GRID - 1) / GRID;   // 1352
        int start = blockIdx.x * chunk;
        int end   = min(start + chunk, total4);
        float4* o4 = (float4*)out;
        for (int i = start + tid; i < end; i += TPB) {
            int b = i / (NENT / 4);                  // 25000 f4 per row
            float iv = sinv_s[b];
            float4 v = o4[i];
            v.x *= iv; v.y *= iv; v.z *= iv; v.w *= iv;
            o4[i] = v;
        }
    }
}

// ---------------- launch ----------------
extern "C" void kernel_launch(void* const* d_in, const int* in_sizes, int n_in,
                              void* d_out, int out_size) {
    const int*   e1     = (const int*)d_in[0];
    const int*   rel    = (const int*)d_in[1];
    // d_in[2]=X, d_in[3]=A unused by the forward pass
    const float* ent    = (const float*)d_in[4];
    const float* relemb = (const float*)d_in[5];
    float* out = (float*)d_out;

    cudaFuncSetAttribute(k_fused, cudaFuncAttributeMaxDynamicSharedMemorySize, SMEM_BYTES);
    k_fused<<<GRID, TPB, SMEM_BYTES>>>(ent, relemb, e1, rel, out);
    (void)in_sizes; (void)n_in; (void)out_size;
}

// round 5
// speedup vs baseline: 1.1031x; 1.1031x over previous
#include <cuda_runtime.h>
#include <cstdint>

typedef unsigned long long ull;

#define NB      16
#define NENT    100000
#define NTILES  3125           // NENT / 32
#define GRID    296            // exactly 2 blocks per SM (148 SMs)
#define TPB     192            // 6 warps
#define NW      6
#define ROWF4   33             // float4 stride per staged row (pad -> conflict-free)
#define XS_F4   (32 * ROWF4)   // per-warp staging float4 count
// dynamic smem: h 8KB + staging NW*1056*16B = 101376 B  => 109568 B
#define SMEM_BYTES (8192 + NW * XS_F4 * 16)

// ---------------- device scratch (allocation-free) ----------------
__device__ float    g_part[NB * GRID];
__device__ unsigned g_ctr;     // tile work queue
__device__ unsigned g_done;    // grid barrier epoch counter (monotonic)

// ---------------- packed f32x2 helpers (sm_103a) ----------------
__device__ __forceinline__ ull add2(ull a, ull b) {
    ull r; asm("add.rn.f32x2 %0,%1,%2;" : "=l"(r) : "l"(a), "l"(b)); return r;
}
__device__ __forceinline__ ull fma2(ull a, ull b, ull c) {
    ull r; asm("fma.rn.f32x2 %0,%1,%2,%3;" : "=l"(r) : "l"(a), "l"(b), "l"(c)); return r;
}
__device__ __forceinline__ ull abs2(ull a) { return a & 0x7FFFFFFF7FFFFFFFull; }
__device__ __forceinline__ ull pk2(float a, float b) {
    ull r; asm("mov.b64 %0,{%1,%2};" : "=l"(r) : "f"(a), "f"(b)); return r;
}
__device__ __forceinline__ float2 upk(ull a) {
    float2 f; asm("mov.b64 {%0,%1},%2;" : "=f"(f.x), "=f"(f.y) : "l"(a)); return f;
}
__device__ __forceinline__ float wsum(float v) {
    #pragma unroll
    for (int o = 16; o; o >>= 1) v += __shfl_xor_sync(0xffffffffu, v, o);
    return v;
}
__device__ __forceinline__ unsigned sm_u32(const void* p) {
    unsigned a;
    asm("{ .reg .u64 t; cvta.to.shared.u64 t, %1; cvt.u32.u64 %0, t; }" : "=r"(a) : "l"(p));
    return a;
}
__device__ __forceinline__ void cpa16(unsigned dst, const void* src) {
    asm volatile("cp.async.cg.shared.global [%0], [%1], 16;" :: "r"(dst), "l"(src));
}

// =============== single fused kernel ===============
__global__ void __launch_bounds__(TPB, 2)
k_fused(const float* __restrict__ ent, const float* __restrict__ relemb,
        const int* __restrict__ e1w, const int* __restrict__ relw,
        float* __restrict__ out) {
    extern __shared__ float smf[];
    float*      hs   = smf;                           // 16*128 floats (8KB), persistent
    ulonglong2* hs2  = (ulonglong2*)smf;              // [16][32] chunks
    float4*     xs4  = (float4*)(smf + 2048);

    int tid = threadIdx.x, w = tid >> 5, l = tid & 31;
    float4*     xw    = xs4 + w * XS_F4;
    unsigned    xw_u  = sm_u32(xw);
    const float4*     myrow  = xw + l * ROWF4;
    const ulonglong2* myrow2 = (const ulonglong2*)myrow;

    __shared__ float sp[NW][NB];
    __shared__ float sinv_s[NB];

    // ---- index width detection (int64 => high words zero) ----
    int odd  = e1w[1] | e1w[3] | e1w[5] | e1w[7] | e1w[9] | e1w[11] | e1w[13] | e1w[15];
    int is64 = (odd == 0);

    // ---- build h = norm(ent[e1[b]]) + norm(rel[rel[b]]) into dedicated smem ----
    for (int b = w; b < NB; b += NW) {
        long long ei, ri;
        if (is64) { ei = ((const long long*)e1w)[b]; ri = ((const long long*)relw)[b]; }
        else      { ei = (long long)e1w[b];          ri = (long long)relw[b]; }
        float4 a = ((const float4*)ent)[(size_t)ei * 32 + l];
        float sa = wsum(fmaf(a.x, a.x, fmaf(a.y, a.y, fmaf(a.z, a.z, a.w * a.w))));
        float ia = rsqrtf(fmaxf(sa, 1e-24f));
        float4 c = ((const float4*)relemb)[(size_t)ri * 32 + l];
        float sc = wsum(fmaf(c.x, c.x, fmaf(c.y, c.y, fmaf(c.z, c.z, c.w * c.w))));
        float ic = rsqrtf(fmaxf(sc, 1e-24f));
        float4 h;
        h.x = fmaf(a.x, ia, c.x * ic);
        h.y = fmaf(a.y, ia, c.y * ic);
        h.z = fmaf(a.z, ia, c.z * ic);
        h.w = fmaf(a.w, ia, c.w * ic);
        ((float4*)hs)[b * 32 + l] = h;
    }
    __syncthreads();

    float es[NB];
    #pragma unroll
    for (int b = 0; b < NB; b++) es[b] = 0.0f;

    // =============== phase 1: dist -> exp -> store ===============
    unsigned t = 0u;
    if (l == 0) t = atomicAdd(&g_ctr, 1u);
    t = __shfl_sync(0xffffffffu, t, 0);

    while (t < (unsigned)NTILES) {
        int base = (int)t * 32;

        // stage 32 entity rows via cp.async (each lane copies 16B per row)
        const char* src = (const char*)ent + (size_t)base * 512 + l * 16;
        #pragma unroll
        for (int r = 0; r < 32; r++)
            cpa16(xw_u + r * (ROWF4 * 16) + l * 16, src + r * 512);
        asm volatile("cp.async.commit_group;");

        // fetch next tile index while the copy is in flight
        unsigned tn = 0u;
        if (l == 0) tn = atomicAdd(&g_ctr, 1u);
        tn = __shfl_sync(0xffffffffu, tn, 0);

        asm volatile("cp.async.wait_group 0;");
        __syncwarp();

        // sumsq of my entity row (lane l owns entity base+l)
        float s0 = 0.f, s1 = 0.f, s2 = 0.f, s3 = 0.f;
        #pragma unroll
        for (int j = 0; j < 32; j += 4) {
            float4 v0 = myrow[j], v1 = myrow[j+1], v2 = myrow[j+2], v3 = myrow[j+3];
            s0 = fmaf(v0.x, v0.x, fmaf(v0.y, v0.y, fmaf(v0.z, v0.z, fmaf(v0.w, v0.w, s0))));
            s1 = fmaf(v1.x, v1.x, fmaf(v1.y, v1.y, fmaf(v1.z, v1.z, fmaf(v1.w, v1.w, s1))));
            s2 = fmaf(v2.x, v2.x, fmaf(v2.y, v2.y, fmaf(v2.z, v2.z, fmaf(v2.w, v2.w, s2))));
            s3 = fmaf(v3.x, v3.x, fmaf(v3.y, v3.y, fmaf(v3.z, v3.z, fmaf(v3.w, v3.w, s3))));
        }
        float ss  = (s0 + s1) + (s2 + s3);
        float inv = -rsqrtf(fmaxf(ss, 1e-24f));   // diff = fma(x, -inv, h)
        ull nI = pk2(inv, inv);

        // 16 independent accumulator chains (one per batch row)
        ull acc[NB];
        #pragma unroll
        for (int b = 0; b < NB; b++) acc[b] = 0ull;

        #pragma unroll 2
        for (int c = 0; c < 32; c++) {            // 32 chunks of 4 dims
            ulonglong2 x = myrow2[c];             // lane-private, conflict-free
            #pragma unroll
            for (int b = 0; b < NB; b++) {
                ulonglong2 hh = hs2[b * 32 + c];  // uniform addr -> broadcast
                acc[b] = add2(acc[b], abs2(fma2(x.x, nI, hh.x)));
                acc[b] = add2(acc[b], abs2(fma2(x.y, nI, hh.y)));
            }
        }

        // exp + store (dist <= ~34: no max pass needed), coalesced per b
        int el = base + l;
        #pragma unroll
        for (int b = 0; b < NB; b++) {
            float2 f = upk(acc[b]);
            float e = __expf(f.x + f.y);
            out[(size_t)b * NENT + el] = e;
            es[b] += e;
        }
        t = tn;
    }

    // ---- warp -> block row sums ----
    #pragma unroll
    for (int b = 0; b < NB; b++) {
        float s = wsum(es[b]);
        if (l == 0) sp[w][b] = s;
    }
    __syncthreads();
    if (tid < NB) {
        float s = 0.f;
        #pragma unroll
        for (int ww = 0; ww < NW; ww++) s += sp[ww][tid];
        g_part[tid * GRID + blockIdx.x] = s;
    }

    // =============== grid-wide barrier (all 296 blocks co-resident) ===============
    __syncthreads();
    if (tid == 0) {
        __threadfence();
        unsigned old = atomicAdd(&g_done, 1u);
        unsigned target = (old / GRID + 1u) * GRID;
        if (old % GRID == GRID - 1u) g_ctr = 0u;   // reset queue for next replay
        unsigned d;
        do {
            asm volatile("ld.global.acquire.gpu.u32 %0, [%1];" : "=r"(d) : "l"(&g_done));
        } while (d < target);
    }
    __syncthreads();

    // ---- reduce partials -> 1/sum per row ----
    for (int b = w; b < NB; b += NW) {
        float s = 0.f;
        for (int i = l; i < GRID; i += 32) s += g_part[b * GRID + i];
        s = wsum(s);
        if (l == 0) sinv_s[b] = 1.0f / s;
    }
    __syncthreads();

    // =============== phase 2: normalize in place (L2-hot) ===============
    {
        const int total4 = NB * NENT / 4;                 // 400000
        const int chunk  = (total4 + GRID - 1) / GRID;    // 1352
        int start = blockIdx.x * chunk;
        int end   = min(start + chunk, total4);
        float4* o4 = (float4*)out;
        for (int i = start + tid; i < end; i += TPB) {
            int b = i / (NENT / 4);
            float iv = sinv_s[b];
            float4 v = o4[i];
            v.x *= iv; v.y *= iv; v.z *= iv; v.w *= iv;
            o4[i] = v;
        }
    }
}

// ---------------- launch ----------------
extern "C" void kernel_launch(void* const* d_in, const int* in_sizes, int n_in,
                              void* d_out, int out_size) {
    const int*   e1     = (const int*)d_in[0];
    const int*   rel    = (const int*)d_in[1];
    // d_in[2]=X, d_in[3]=A unused by the forward pass
    const float* ent    = (const float*)d_in[4];
    const float* relemb = (const float*)d_in[5];
    float* out = (float*)d_out;

    cudaFuncSetAttribute(k_fused, cudaFuncAttributeMaxDynamicSharedMemorySize, SMEM_BYTES);
    k_fused<<<GRID, TPB, SMEM_BYTES>>>(ent, relemb, e1, rel, out);
    (void)in_sizes; (void)n_in; (void)out_size;
}

// round 6
// speedup vs baseline: 1.1566x; 1.0485x over previous
#include <cuda_runtime.h>
#include <cstdint>

typedef unsigned long long ull;

#define NB      16
#define NENT    100000
#define NTILES  3125           // NENT / 32
#define GRID    296            // 2 blocks per SM
#define TPB     320            // 10 warps = 5 pairs
#define NW      10
#define NPAIR   5
#define ROWF4   33             // float4 per staged row (32 data + 1 pad)
#define PAIR_F4 (32 * ROWF4)   // 1056 float4 per pair tile
// dynamic smem: h 8192 B + 5 pairs * 16896 B = 92672 B
#define SMEM_BYTES (8192 + NPAIR * PAIR_F4 * 16)

// ---------------- device scratch (allocation-free) ----------------
__device__ float    g_part[NB * GRID];
__device__ unsigned g_ctr;     // tile work queue
__device__ unsigned g_done;    // grid barrier epoch counter (monotonic)

// ---------------- packed f32x2 helpers (sm_103a) ----------------
__device__ __forceinline__ ull add2(ull a, ull b) {
    ull r; asm("add.rn.f32x2 %0,%1,%2;" : "=l"(r) : "l"(a), "l"(b)); return r;
}
__device__ __forceinline__ ull fma2(ull a, ull b, ull c) {
    ull r; asm("fma.rn.f32x2 %0,%1,%2,%3;" : "=l"(r) : "l"(a), "l"(b), "l"(c)); return r;
}
__device__ __forceinline__ ull abs2(ull a) { return a & 0x7FFFFFFF7FFFFFFFull; }
__device__ __forceinline__ ull pk2(float a, float b) {
    ull r; asm("mov.b64 %0,{%1,%2};" : "=l"(r) : "f"(a), "f"(b)); return r;
}
__device__ __forceinline__ float2 upk(ull a) {
    float2 f; asm("mov.b64 {%0,%1},%2;" : "=f"(f.x), "=f"(f.y) : "l"(a)); return f;
}
__device__ __forceinline__ float wsum(float v) {
    #pragma unroll
    for (int o = 16; o; o >>= 1) v += __shfl_xor_sync(0xffffffffu, v, o);
    return v;
}
__device__ __forceinline__ unsigned sm_u32(const void* p) {
    unsigned a;
    asm("{ .reg .u64 t; cvta.to.shared.u64 t, %1; cvt.u32.u64 %0, t; }" : "=r"(a) : "l"(p));
    return a;
}
__device__ __forceinline__ void cpa16(unsigned dst, const void* src) {
    asm volatile("cp.async.cg.shared.global [%0], [%1], 16;" :: "r"(dst), "l"(src));
}
__device__ __forceinline__ void barp(int id) {
    asm volatile("bar.sync %0, 64;" :: "r"(id) : "memory");
}

// =============== single fused kernel ===============
__global__ void __launch_bounds__(TPB, 2)
k_fused(const float* __restrict__ ent, const float* __restrict__ relemb,
        const int* __restrict__ e1w, const int* __restrict__ relw,
        float* __restrict__ out) {
    extern __shared__ float smf[];
    float*      hs   = smf;                           // 16*128 floats, persistent
    ulonglong2* hs2  = (ulonglong2*)smf;              // [16][32] 16B chunks

    int tid = threadIdx.x, w = tid >> 5, l = tid & 31;
    int p = w >> 1, role = w & 1;                     // pair id, b-half role

    float4*     xs4  = (float4*)(smf + 2048) + p * PAIR_F4;
    ulonglong2* xs2  = (ulonglong2*)xs4;
    unsigned    xw_u = sm_u32(xs4);

    __shared__ float    invb[NPAIR][32];
    __shared__ unsigned tsl[NPAIR];
    __shared__ float    sp[NW][8];
    __shared__ float    sinv_s[NB];

    // ---- index width detection (int64 => high words zero) ----
    int odd  = e1w[1] | e1w[3] | e1w[5] | e1w[7] | e1w[9] | e1w[11] | e1w[13] | e1w[15];
    int is64 = (odd == 0);

    // ---- build h = norm(ent[e1[b]]) + norm(rel[rel[b]]) ----
    for (int b = w; b < NB; b += NW) {
        long long ei, ri;
        if (is64) { ei = ((const long long*)e1w)[b]; ri = ((const long long*)relw)[b]; }
        else      { ei = (long long)e1w[b];          ri = (long long)relw[b]; }
        float4 a = ((const float4*)ent)[(size_t)ei * 32 + l];
        float sa = wsum(fmaf(a.x, a.x, fmaf(a.y, a.y, fmaf(a.z, a.z, a.w * a.w))));
        float ia = rsqrtf(fmaxf(sa, 1e-24f));
        float4 c = ((const float4*)relemb)[(size_t)ri * 32 + l];
        float sc = wsum(fmaf(c.x, c.x, fmaf(c.y, c.y, fmaf(c.z, c.z, c.w * c.w))));
        float ic = rsqrtf(fmaxf(sc, 1e-24f));
        float4 h;
        h.x = fmaf(a.x, ia, c.x * ic);
        h.y = fmaf(a.y, ia, c.y * ic);
        h.z = fmaf(a.z, ia, c.z * ic);
        h.w = fmaf(a.w, ia, c.w * ic);
        ((float4*)hs)[b * 32 + l] = h;
    }
    __syncthreads();

    float es[8];
    #pragma unroll
    for (int j = 0; j < 8; j++) es[j] = 0.0f;
    const int bq = role * 8;                          // my b range: bq..bq+7

    // ---- initial tile fetch (role-0 warp publishes to the pair) ----
    if (role == 0 && l == 0) tsl[p] = atomicAdd(&g_ctr, 1u);
    barp(p + 1);
    unsigned t = tsl[p];

    // =============== phase 1: dist -> exp -> store ===============
    while (t < (unsigned)NTILES) {
        int base = (int)t * 32;

        // stage my role's 16 rows (coalesced 512B per row, lane l copies chunk l)
        {
            const char* src = (const char*)ent + ((size_t)base + role * 16) * 512 + l * 16;
            unsigned    dst = xw_u + (unsigned)((role * 16) * ROWF4 + l) * 16;
            #pragma unroll
            for (int k = 0; k < 16; k++)
                cpa16(dst + k * (ROWF4 * 16), src + (size_t)k * 512);
            asm volatile("cp.async.commit_group;");
        }
        // prefetch next tile index while copies are in flight
        if (role == 0 && l == 0) tsl[p] = atomicAdd(&g_ctr, 1u);
        asm volatile("cp.async.wait_group 0;");
        barp(p + 1);                                   // staged tile + tsl visible
        unsigned tn = tsl[p];

        // inv norms for my role's 16 rows (2 lanes per row, half each)
        {
            int row  = role * 16 + (l >> 1);
            int half = l & 1;
            const float4* rp = xs4 + row * ROWF4 + half * 16;
            float s0 = 0.f, s1 = 0.f, s2 = 0.f, s3 = 0.f;
            #pragma unroll
            for (int q = 0; q < 16; q += 4) {
                float4 v0 = rp[q], v1 = rp[q+1], v2 = rp[q+2], v3 = rp[q+3];
                s0 = fmaf(v0.x, v0.x, fmaf(v0.y, v0.y, fmaf(v0.z, v0.z, fmaf(v0.w, v0.w, s0))));
                s1 = fmaf(v1.x, v1.x, fmaf(v1.y, v1.y, fmaf(v1.z, v1.z, fmaf(v1.w, v1.w, s1))));
                s2 = fmaf(v2.x, v2.x, fmaf(v2.y, v2.y, fmaf(v2.z, v2.z, fmaf(v2.w, v2.w, s2))));
                s3 = fmaf(v3.x, v3.x, fmaf(v3.y, v3.y, fmaf(v3.z, v3.z, fmaf(v3.w, v3.w, s3))));
            }
            float ss = (s0 + s1) + (s2 + s3);
            ss += __shfl_xor_sync(0xffffffffu, ss, 1);
            if (half == 0) invb[p][row] = -rsqrtf(fmaxf(ss, 1e-24f));
        }
        barp(p + 1);                                   // all 32 invs visible

        float iv = invb[p][l];                         // lane l owns entity base+l
        ull  nI = pk2(iv, iv);

        ull acc[8];
        #pragma unroll
        for (int j = 0; j < 8; j++) acc[j] = 0ull;

        #pragma unroll 2
        for (int c = 0; c < 32; c++) {                 // 32 chunks of 4 dims
            ulonglong2 x = xs2[l * ROWF4 + c];         // lane-private, conflict-free
            #pragma unroll
            for (int j = 0; j < 8; j++) {
                ulonglong2 hh = hs2[(bq + j) * 32 + c];  // uniform -> broadcast
                acc[j] = add2(acc[j], abs2(fma2(x.x, nI, hh.x)));
                acc[j] = add2(acc[j], abs2(fma2(x.y, nI, hh.y)));
            }
        }

        // exp + store (dist <= ~34: no max pass), fully coalesced per b
        int el = base + l;
        #pragma unroll
        for (int j = 0; j < 8; j++) {
            float2 f = upk(acc[j]);
            float e = __expf(f.x + f.y);
            out[(size_t)(bq + j) * NENT + el] = e;
            es[j] += e;
        }

        barp(p + 1);                                   // both warps done reading staging
        t = tn;
    }

    // ---- warp -> block row sums ----
    #pragma unroll
    for (int j = 0; j < 8; j++) {
        float s = wsum(es[j]);
        if (l == 0) sp[w][j] = s;
    }
    __syncthreads();
    if (tid < NB) {
        int b = tid, r = b >> 3, j = b & 7;
        float s = 0.f;
        #pragma unroll
        for (int k = 0; k < NPAIR; k++) s += sp[2 * k + r][j];
        g_part[b * GRID + blockIdx.x] = s;
    }

    // =============== grid-wide barrier (all 296 blocks co-resident) ===============
    __syncthreads();
    if (tid == 0) {
        __threadfence();
        unsigned old = atomicAdd(&g_done, 1u);
        unsigned target = (old / GRID + 1u) * GRID;
        if (old % GRID == GRID - 1u) g_ctr = 0u;       // reset queue for next replay
        unsigned d;
        do {
            asm volatile("ld.global.acquire.gpu.u32 %0, [%1];" : "=r"(d) : "l"(&g_done));
        } while (d < target);
    }
    __syncthreads();

    // ---- reduce partials -> 1/sum per row ----
    for (int b = w; b < NB; b += NW) {
        float s = 0.f;
        for (int i = l; i < GRID; i += 32) s += g_part[b * GRID + i];
        s = wsum(s);
        if (l == 0) sinv_s[b] = 1.0f / s;
    }
    __syncthreads();

    // =============== phase 2: normalize in place (L2-hot) ===============
    {
        const int total4 = NB * NENT / 4;              // 400000
        const int chunk  = (total4 + GRID - 1) / GRID; // 1352
        int start = blockIdx.x * chunk;
        int end   = min(start + chunk, total4);
        float4* o4 = (float4*)out;
        for (int i = start + tid; i < end; i += TPB) {
            int b = i / (NENT / 4);
            float iv = sinv_s[b];
            float4 v = o4[i];
            v.x *= iv; v.y *= iv; v.z *= iv; v.w *= iv;
            o4[i] = v;
        }
    }
}

// ---------------- launch ----------------
extern "C" void kernel_launch(void* const* d_in, const int* in_sizes, int n_in,
                              void* d_out, int out_size) {
    const int*   e1     = (const int*)d_in[0];
    const int*   rel    = (const int*)d_in[1];
    // d_in[2]=X, d_in[3]=A unused by the forward pass
    const float* ent    = (const float*)d_in[4];
    const float* relemb = (const float*)d_in[5];
    float* out = (float*)d_out;

    cudaFuncSetAttribute(k_fused, cudaFuncAttributeMaxDynamicSharedMemorySize, SMEM_BYTES);
    k_fused<<<GRID, TPB, SMEM_BYTES>>>(ent, relemb, e1, rel, out);
    (void)in_sizes; (void)n_in; (void)out_size;
}